// round 1
// baseline (speedup 1.0000x reference)
#include <cuda_runtime.h>
#include <cuda_bf16.h>
#include <math.h>

// Problem constants
#define BB 8
#define NN 512
#define CC 37
#define CF 36        // foreground classes
#define DD 2048
#define SCORE_THR 0.1f
#define NMS_THR 0.4f

// Output layout (float32, reference return order, flattened+concatenated):
//   cls_dets  [B, CF, N, 5]  : 737280 floats, offset 0
//   kept_feats[B, N, D]      : 8388608 floats, offset 737280
//   keep      [B, CF, N]     : 147456 floats (0/1), offset 9125888
#define OUT_DETS_OFF   0
#define OUT_FEATS_OFF  737280
#define OUT_KEEP_OFF   9125888

// Scratch (no allocations allowed -> __device__ globals)
__device__ float g_boxes[BB * CF * NN * 4];   // class-major decoded+clipped boxes
__device__ float g_scores[BB * CF * NN];      // class-major fg scores
__device__ int   g_anykeep[BB * NN];          // per-roi any-class keep flag

// ---------------------------------------------------------------------------
// Kernel 1: box decode (delta * stds, transform_inv, clip) -> class-major
// Also zeros g_anykeep.
// ---------------------------------------------------------------------------
__global__ void decode_kernel(const float* __restrict__ rois,
                              const float* __restrict__ bbox_pred,
                              const float* __restrict__ scores,
                              const float* __restrict__ im_info) {
    int t = blockIdx.x * blockDim.x + threadIdx.x;
    if (t < BB * NN) g_anykeep[t] = 0;
    if (t >= BB * CF * NN) return;

    // t = (b*CF + c)*NN + n   (class-major so NMS blocks read contiguous)
    int n = t % NN;
    int c = (t / NN) % CF;         // fg class index 0..35 -> real class c+1
    int b = t / (NN * CF);

    const float* r = rois + (b * NN + n) * 5;
    float rx1 = r[1], ry1 = r[2], rx2 = r[3], ry2 = r[4];
    float w  = rx2 - rx1;
    float h  = ry2 - ry1;
    float cx = rx1 + 0.5f * w;
    float cy = ry1 + 0.5f * h;

    const float* dp = bbox_pred + ((b * NN + n) * CC + (c + 1)) * 4;
    float d0 = dp[0] * 0.1f;
    float d1 = dp[1] * 0.1f;
    float d2 = dp[2] * 0.2f;
    float d3 = dp[3] * 0.2f;

    float px = d0 * w + cx;
    float py = d1 * h + cy;
    float pw = expf(d2) * w;
    float ph = expf(d3) * h;

    float x1 = px - 0.5f * pw;
    float y1 = py - 0.5f * ph;
    float x2 = px + 0.5f * pw;
    float y2 = py + 0.5f * ph;

    float xmax = im_info[b * 3 + 1] - 1.0f;
    float ymax = im_info[b * 3 + 0] - 1.0f;
    x1 = fminf(fmaxf(x1, 0.0f), xmax);
    y1 = fminf(fmaxf(y1, 0.0f), ymax);
    x2 = fminf(fmaxf(x2, 0.0f), xmax);
    y2 = fminf(fmaxf(y2, 0.0f), ymax);

    float* bo = g_boxes + (size_t)t * 4;
    bo[0] = x1; bo[1] = y1; bo[2] = x2; bo[3] = y2;
    g_scores[t] = scores[(b * NN + n) * CC + (c + 1)];
}

// float -> order-preserving unsigned
__device__ __forceinline__ unsigned f2ord(float f) {
    unsigned u = __float_as_uint(f);
    return (u & 0x80000000u) ? ~u : (u | 0x80000000u);
}

// ---------------------------------------------------------------------------
// Kernel 2: per-(b,class) greedy NMS. One block = one (b,c). 512 threads.
// Writes cls_dets, keep output, and g_anykeep.
// ---------------------------------------------------------------------------
__global__ __launch_bounds__(512) void nms_kernel(float* __restrict__ out) {
    __shared__ unsigned long long comp[NN];
    __shared__ float x1s[NN], y1s[NN], x2s[NN], y2s[NN], areas[NN];
    __shared__ int keepflag[NN];

    int tid = threadIdx.x;
    int bc  = blockIdx.x;                 // b*CF + c
    const float* sc = g_scores + (size_t)bc * NN;
    const float* bx = g_boxes  + (size_t)bc * NN * 4;

    float s = sc[tid];
    bool valid = s > SCORE_THR;
    int vc = __syncthreads_count(valid);  // number of valid boxes

    // composite key: ascending sort => score desc, idx asc tiebreak (stable)
    float key = valid ? s : -INFINITY;
    comp[tid] = ((unsigned long long)(~f2ord(key)) << 32) | (unsigned)tid;

    // bitonic sort, 512 elems, 512 threads, ascending
    for (int k = 2; k <= NN; k <<= 1) {
        for (int j = k >> 1; j > 0; j >>= 1) {
            __syncthreads();
            int ixj = tid ^ j;
            if (ixj > tid) {
                bool asc = ((tid & k) == 0);
                unsigned long long a = comp[tid], b2 = comp[ixj];
                if ((a > b2) == asc) { comp[tid] = b2; comp[ixj] = a; }
            }
        }
    }
    __syncthreads();

    int orig = (int)(comp[tid] & 0xFFFFFFFFu);
    const float* bp = bx + (size_t)orig * 4;
    float mx1 = bp[0], my1 = bp[1], mx2 = bp[2], my2 = bp[3];
    float marea = (mx2 - mx1) * (my2 - my1);
    float ssort = sc[orig];

    x1s[tid] = mx1; y1s[tid] = my1; x2s[tid] = mx2; y2s[tid] = my2;
    areas[tid] = marea;
    keepflag[tid] = 0;
    __syncthreads();

    // greedy: only the valid prefix can ever be kept
    for (int i = 0; i < vc; i++) {
        bool sup = false;
        if (tid < i && keepflag[tid]) {
            float ix1 = x1s[i], iy1 = y1s[i], ix2 = x2s[i], iy2 = y2s[i];
            float ia  = areas[i];
            float lx = fmaxf(mx1, ix1);
            float ly = fmaxf(my1, iy1);
            float rx = fminf(mx2, ix2);
            float ry = fminf(my2, iy2);
            float iw = fmaxf(rx - lx, 0.0f);
            float ih = fmaxf(ry - ly, 0.0f);
            float inter = iw * ih;
            float iou = inter / (marea + ia - inter + 1e-9f);
            sup = iou > NMS_THR;
        }
        bool any = __syncthreads_or((int)sup) != 0;
        if (tid == i) keepflag[i] = any ? 0 : 1;
        __syncthreads();
    }

    // write outputs in original roi order (each sorted pos -> unique orig n)
    bool k = (tid < vc) && (keepflag[tid] != 0);
    size_t det_base = (size_t)OUT_DETS_OFF + ((size_t)bc * NN + orig) * 5;
    if (k) {
        out[det_base + 0] = mx1;
        out[det_base + 1] = my1;
        out[det_base + 2] = mx2;
        out[det_base + 3] = my2;
        out[det_base + 4] = ssort;
    } else {
        out[det_base + 0] = 0.0f;
        out[det_base + 1] = 0.0f;
        out[det_base + 2] = 0.0f;
        out[det_base + 3] = 0.0f;
        out[det_base + 4] = 0.0f;
    }
    out[(size_t)OUT_KEEP_OFF + (size_t)bc * NN + orig] = k ? 1.0f : 0.0f;
    if (k) {
        int b = bc / CF;
        atomicOr(&g_anykeep[b * NN + orig], 1);
    }
}

// ---------------------------------------------------------------------------
// Kernel 3: masked feature copy (HBM-bound, float4 vectorized)
// ---------------------------------------------------------------------------
__global__ void feats_kernel(const float4* __restrict__ feats,
                             float4* __restrict__ out4) {
    int i = blockIdx.x * blockDim.x + threadIdx.x;
    const int total4 = BB * NN * DD / 4;   // 2,097,152
    if (i >= total4) return;
    int bn = i >> (11 - 2);                // i / (D/4) = i / 512 -> wrong; fix below
    bn = i / (DD / 4);
    float4 v = feats[i];
    if (!g_anykeep[bn]) { v.x = 0.f; v.y = 0.f; v.z = 0.f; v.w = 0.f; }
    out4[i] = v;
}

extern "C" void kernel_launch(void* const* d_in, const int* in_sizes, int n_in,
                              void* d_out, int out_size) {
    const float* rois      = (const float*)d_in[0];
    const float* bbox_pred = (const float*)d_in[1];
    const float* scores    = (const float*)d_in[2];
    const float* im_info   = (const float*)d_in[3];
    const float* feats     = (const float*)d_in[4];
    float* out = (float*)d_out;

    int decode_threads = BB * CF * NN;   // 147456 (also covers anykeep zeroing)
    decode_kernel<<<(decode_threads + 255) / 256, 256>>>(rois, bbox_pred, scores, im_info);

    nms_kernel<<<BB * CF, 512>>>(out);

    const int total4 = BB * NN * DD / 4;
    feats_kernel<<<(total4 + 255) / 256, 256>>>(
        (const float4*)feats, (float4*)(out + OUT_FEATS_OFF));
}

// round 2
// speedup vs baseline: 1.0718x; 1.0718x over previous
#include <cuda_runtime.h>
#include <cuda_bf16.h>
#include <math.h>

// Problem constants
#define BB 8
#define NN 512
#define CC 37
#define CF 36        // foreground classes
#define DD 2048
#define SCORE_THR 0.1f
#define NMS_THR 0.4f

// Output layout (float32, reference return order, flattened+concatenated):
//   cls_dets  [B, CF, N, 5]  : 737280 floats, offset 0
//   kept_feats[B, N, D]      : 8388608 floats, offset 737280
//   keep      [B, CF, N]     : 147456 floats (0/1), offset 9125888
#define OUT_DETS_OFF   0
#define OUT_FEATS_OFF  737280
#define OUT_KEEP_OFF   9125888

// float -> order-preserving unsigned (valid only for finite floats)
__device__ __forceinline__ unsigned f2ord(float f) {
    unsigned u = __float_as_uint(f);
    return (u & 0x80000000u) ? ~u : (u | 0x80000000u);
}

// ---------------------------------------------------------------------------
// Kernel 1: fused decode + greedy NMS. One block = one (b, fg-class).
// Only boxes with score > SCORE_THR are decoded/sorted/tested (expected ~35
// of 512). Rank-by-counting replaces the full bitonic sort.
// Writes cls_dets and keep sections of out.
// ---------------------------------------------------------------------------
__global__ __launch_bounds__(512) void nms_fused_kernel(
    const float* __restrict__ rois,
    const float* __restrict__ bbox_pred,
    const float* __restrict__ scores,
    const float* __restrict__ im_info,
    float* __restrict__ out)
{
    __shared__ unsigned long long keys[NN];   // compacted valid keys (unordered)
    __shared__ float sx1[NN], sy1[NN], sx2[NN], sy2[NN], sar[NN];  // sorted boxes
    __shared__ int   keepflag[NN];            // keep decision per sorted pos
    __shared__ int   cnt;

    int tid = threadIdx.x;
    int bc  = blockIdx.x;          // b*CF + c
    int c   = bc % CF;             // fg class -> real class c+1
    int b   = bc / CF;

    if (tid == 0) cnt = 0;
    __syncthreads();

    float s = scores[(b * NN + tid) * CC + (c + 1)];
    bool valid = s > SCORE_THR;

    // key: higher score first; tie -> lower original index first (stable argsort)
    unsigned long long mycomp = 0ull;
    if (valid) {
        mycomp = ((unsigned long long)f2ord(s) << 32) | (unsigned)(NN - 1 - tid);
        int pos = atomicAdd(&cnt, 1);
        keys[pos] = mycomp;
    }
    __syncthreads();
    int vc = cnt;

    // decode own box + compute rank among valid (only valid threads)
    float mx1 = 0.f, my1 = 0.f, mx2 = 0.f, my2 = 0.f, marea = 0.f;
    int rank = -1;
    if (valid) {
        int r = 0;
        for (int j = 0; j < vc; j++) r += (keys[j] > mycomp);
        rank = r;

        const float* rr = rois + (b * NN + tid) * 5;
        float rx1 = rr[1], ry1 = rr[2], rx2 = rr[3], ry2 = rr[4];
        float w  = rx2 - rx1;
        float h  = ry2 - ry1;
        float cx = rx1 + 0.5f * w;
        float cy = ry1 + 0.5f * h;

        const float* dp = bbox_pred + ((b * NN + tid) * CC + (c + 1)) * 4;
        float d0 = dp[0] * 0.1f;
        float d1 = dp[1] * 0.1f;
        float d2 = dp[2] * 0.2f;
        float d3 = dp[3] * 0.2f;

        float px = d0 * w + cx;
        float py = d1 * h + cy;
        float pw = expf(d2) * w;
        float ph = expf(d3) * h;

        float xmax = im_info[b * 3 + 1] - 1.0f;
        float ymax = im_info[b * 3 + 0] - 1.0f;
        mx1 = fminf(fmaxf(px - 0.5f * pw, 0.0f), xmax);
        my1 = fminf(fmaxf(py - 0.5f * ph, 0.0f), ymax);
        mx2 = fminf(fmaxf(px + 0.5f * pw, 0.0f), xmax);
        my2 = fminf(fmaxf(py + 0.5f * ph, 0.0f), ymax);
        marea = (mx2 - mx1) * (my2 - my1);

        sx1[rank] = mx1; sy1[rank] = my1;
        sx2[rank] = mx2; sy2[rank] = my2;
        sar[rank] = marea;
    }
    __syncthreads();

    // greedy NMS over the valid, sorted prefix
    for (int i = 0; i < vc; i++) {
        bool sup = false;
        if (valid && rank < i && keepflag[rank]) {
            float lx = fmaxf(mx1, sx1[i]);
            float ly = fmaxf(my1, sy1[i]);
            float rx = fminf(mx2, sx2[i]);
            float ry = fminf(my2, sy2[i]);
            float iw = fmaxf(rx - lx, 0.0f);
            float ih = fmaxf(ry - ly, 0.0f);
            float inter = iw * ih;
            float iou = inter / (marea + sar[i] - inter + 1e-9f);
            sup = iou > NMS_THR;
        }
        int any = __syncthreads_or((int)sup);
        if (rank == i) keepflag[i] = any ? 0 : 1;
        __syncthreads();
    }

    bool k = valid && (keepflag[rank] != 0);

    // outputs in original roi order; every thread writes its slot
    size_t det_base = (size_t)OUT_DETS_OFF + ((size_t)bc * NN + tid) * 5;
    if (k) {
        out[det_base + 0] = mx1;
        out[det_base + 1] = my1;
        out[det_base + 2] = mx2;
        out[det_base + 3] = my2;
        out[det_base + 4] = s;
    } else {
        out[det_base + 0] = 0.0f;
        out[det_base + 1] = 0.0f;
        out[det_base + 2] = 0.0f;
        out[det_base + 3] = 0.0f;
        out[det_base + 4] = 0.0f;
    }
    out[(size_t)OUT_KEEP_OFF + (size_t)bc * NN + tid] = k ? 1.0f : 0.0f;
}

// ---------------------------------------------------------------------------
// Kernel 2: masked feature copy. One block per (b,n) row; row mask derived
// from the keep section already written by kernel 1. Non-kept rows are
// store-only (no feature read).
// ---------------------------------------------------------------------------
__global__ __launch_bounds__(256) void feats_kernel(
    const float4* __restrict__ feats,
    float* __restrict__ out)
{
    int bn = blockIdx.x;           // b*NN + n
    int b  = bn / NN;
    int n  = bn % NN;
    int tid = threadIdx.x;

    bool has = false;
    if (tid < CF)
        has = out[(size_t)OUT_KEEP_OFF + ((size_t)(b * CF + tid)) * NN + n] != 0.0f;
    int any = __syncthreads_or((int)has);

    const float4* src = feats + (size_t)bn * (DD / 4);
    float4* dst = (float4*)(out + OUT_FEATS_OFF) + (size_t)bn * (DD / 4);

    if (any) {
        #pragma unroll
        for (int i = 0; i < DD / 4 / 256; i++) {
            int idx = tid + i * 256;
            dst[idx] = src[idx];
        }
    } else {
        float4 z = make_float4(0.f, 0.f, 0.f, 0.f);
        #pragma unroll
        for (int i = 0; i < DD / 4 / 256; i++) {
            int idx = tid + i * 256;
            dst[idx] = z;
        }
    }
}

extern "C" void kernel_launch(void* const* d_in, const int* in_sizes, int n_in,
                              void* d_out, int out_size) {
    const float* rois      = (const float*)d_in[0];
    const float* bbox_pred = (const float*)d_in[1];
    const float* scores    = (const float*)d_in[2];
    const float* im_info   = (const float*)d_in[3];
    const float* feats     = (const float*)d_in[4];
    float* out = (float*)d_out;

    nms_fused_kernel<<<BB * CF, 512>>>(rois, bbox_pred, scores, im_info, out);
    feats_kernel<<<BB * NN, 256>>>((const float4*)feats, out);
}